// round 8
// baseline (speedup 1.0000x reference)
#include <cuda_runtime.h>

// Problem constants (fixed by the dataset)
#define BB 32
#define LL 1024
#define HH 384
#define H4 (HH / 4)          // 96 float4 per row
#define MAX_DUR 8
#define RPT 8                // rows per thread
#define TILE_T 32            // rows per block (4 y-slices * 8)

// ---------------------------------------------------------------------------
// Fused kernel: each block recomputes the (cheap) duration scan for its batch
// in SMEM, scatters source indices for its 32-row window, then does the
// gather/expand with MLP=8 and streaming stores. No global scratch, one launch.
// Block (96,4) = 384 threads; grid (ceil(T/32), B).
// ---------------------------------------------------------------------------
__global__ void __launch_bounds__(384, 3)
lr_fused_kernel(const float* __restrict__ hid,
                const int* __restrict__ dur,
                float* __restrict__ out,
                float* __restrict__ mask,
                int T) {
    const int lane = threadIdx.x;                 // 0..95
    const int tl = threadIdx.y * H4 + lane;       // 0..383 flat (= hw linear id)
    const int b = blockIdx.y;
    const int w0 = blockIdx.x * TILE_T;           // tile window [w0, w0+32)

    __shared__ int s_idx[TILE_T];
    __shared__ int s_wpre[4];
    __shared__ int s_total;

    if (tl < TILE_T) s_idx[tl] = 0;

    // ---- Phase A: scan + scatter (warps 0-3 only: 128 threads x 8 durs) ----
    int d0, d1, d2, d3, d4, d5, d6, d7;
    int inc = 0, sum = 0;
    if (tl < 128) {
        const int4* dp = (const int4*)(dur + b * LL + tl * 8);
        int4 a0 = dp[0], a1 = dp[1];
        d0 = a0.x; d1 = a0.y; d2 = a0.z; d3 = a0.w;
        d4 = a1.x; d5 = a1.y; d6 = a1.z; d7 = a1.w;
        sum = d0 + d1 + d2 + d3 + d4 + d5 + d6 + d7;
        inc = sum;
        #pragma unroll
        for (int o = 1; o < 32; o <<= 1) {
            int y = __shfl_up_sync(0xFFFFFFFFu, inc, o);
            if ((tl & 31) >= o) inc += y;
        }
        if ((tl & 31) == 31) s_wpre[tl >> 5] = inc;
    }
    __syncthreads();

    if (tl < 128) {
        const int w = tl >> 5;
        int base = 0;
        if (w > 0) base += s_wpre[0];
        if (w > 1) base += s_wpre[1];
        if (w > 2) base += s_wpre[2];

        int run = base + inc - sum;   // exclusive prefix before my 8 elements
        const int w1 = w0 + TILE_T;
        const int j0 = tl * 8;
        int dd[8] = {d0, d1, d2, d3, d4, d5, d6, d7};
        #pragma unroll
        for (int k = 0; k < 8; k++) {
            const int s = run;
            const int e = run + dd[k];
            run = e;
            int lo = s > w0 ? s : w0;
            int hi = e < w1 ? e : w1;
            for (int t = lo; t < hi; t++) s_idx[t - w0] = j0 + k;
        }
        if (tl == 127) s_total = run;  // = cum[L-1] = total frames of batch b
    }
    __syncthreads();

    // ---- Phase B: expand 8 contiguous rows per thread ----
    const int t0 = w0 + threadIdx.y * RPT;
    if (t0 >= T) return;

    const int total = s_total;

    int idx[RPT];
    #pragma unroll
    for (int k = 0; k < RPT; k++) idx[k] = s_idx[threadIdx.y * RPT + k];

    const float4* __restrict__ src =
        (const float4*)(hid) + (long long)b * LL * H4 + lane;
    const float4 z = make_float4(0.f, 0.f, 0.f, 0.f);

    float4 v[RPT];
    #pragma unroll
    for (int k = 0; k < RPT; k++) {
        float4 vv = z;
        if (t0 + k < total) vv = src[idx[k] * H4];
        v[k] = vv;
    }

    float4* __restrict__ dst =
        (float4*)(out) + ((long long)b * T + t0) * H4 + lane;

    if (t0 + RPT <= T) {
        #pragma unroll
        for (int k = 0; k < RPT; k++) __stcs(dst + k * H4, v[k]);

        if (lane == 0) {
            float4 m0, m1;
            m0.x = (t0 + 0 < total) ? 1.f : 0.f;
            m0.y = (t0 + 1 < total) ? 1.f : 0.f;
            m0.z = (t0 + 2 < total) ? 1.f : 0.f;
            m0.w = (t0 + 3 < total) ? 1.f : 0.f;
            m1.x = (t0 + 4 < total) ? 1.f : 0.f;
            m1.y = (t0 + 5 < total) ? 1.f : 0.f;
            m1.z = (t0 + 6 < total) ? 1.f : 0.f;
            m1.w = (t0 + 7 < total) ? 1.f : 0.f;
            float4* mp = (float4*)(mask + (long long)b * T + t0);
            __stcs(mp, m0);
            __stcs(mp + 1, m1);
        }
    } else {
        // T-tail: per-row bounds
        #pragma unroll
        for (int k = 0; k < RPT; k++) {
            if (t0 + k < T) {
                __stcs(dst + k * H4, v[k]);
                if (lane == 0)
                    mask[(long long)b * T + t0 + k] = (t0 + k < total) ? 1.f : 0.f;
            }
        }
    }
}

// ---------------------------------------------------------------------------
extern "C" void kernel_launch(void* const* d_in, const int* in_sizes, int n_in,
                              void* d_out, int out_size) {
    const float* hid = (const float*)d_in[0];   // (B, L, H) f32
    const int*   dur = (const int*)d_in[1];     // (B, L) i32

    // out_size = B*T*H + B*T = B*T*(H+1)
    const int T = out_size / (BB * (HH + 1));
    const long long n_rows = (long long)BB * T;

    float* out  = (float*)d_out;                // B*T*H
    float* mask = (float*)d_out + n_rows * HH;  // B*T

    dim3 grid((T + TILE_T - 1) / TILE_T, BB);
    dim3 blk(H4, 4);
    lr_fused_kernel<<<grid, blk>>>(hid, dur, out, mask, T);
}

// round 9
// speedup vs baseline: 1.0507x; 1.0507x over previous
#include <cuda_runtime.h>

// Problem constants (fixed by the dataset)
#define BB 32
#define LL 1024
#define HH 384
#define H4 (HH / 4)          // 96 float4 per row
#define MAX_DUR 8
#define T_MAX (LL * (MAX_DUR - 1))   // 7168, multiple of 4 -> int4-aligned rows
#define RPT 8                // rows per thread
#define TILE_T 32            // rows per block (4 y-slices * 8)

// Scratch (no cudaMalloc allowed). Row stride is T_MAX so every int4 idx
// load is aligned regardless of runtime T. Unwritten entries stay 0 (safe).
__device__ __align__(16) int g_idx[BB * T_MAX];
__device__ int g_total[BB];

// ---------------------------------------------------------------------------
// Kernel 1: per-batch inclusive scan of durations + scatter of source index
// into g_idx[b*T_MAX + t] for t in [cum-dur, cum).
// ---------------------------------------------------------------------------
__global__ void lr_scan_scatter_kernel(const int* __restrict__ dur) {
    const int b = blockIdx.x;
    const int tid = threadIdx.x;            // 0..1023
    const int lane = tid & 31;
    const int wid = tid >> 5;

    const int d = dur[b * LL + tid];
    int x = d;

    #pragma unroll
    for (int o = 1; o < 32; o <<= 1) {
        int y = __shfl_up_sync(0xFFFFFFFFu, x, o);
        if (lane >= o) x += y;
    }

    __shared__ int wsum[32];
    if (lane == 31) wsum[wid] = x;
    __syncthreads();

    if (wid == 0) {
        int s = wsum[lane];
        #pragma unroll
        for (int o = 1; o < 32; o <<= 1) {
            int y = __shfl_up_sync(0xFFFFFFFFu, s, o);
            if (lane >= o) s += y;
        }
        wsum[lane] = s;
    }
    __syncthreads();

    if (wid > 0) x += wsum[wid - 1];        // inclusive cumsum at position tid

    int* __restrict__ idx_row = g_idx + b * T_MAX;
    const int start = x - d;
    #pragma unroll
    for (int k = 0; k < MAX_DUR; k++) {
        if (k < d) idx_row[start + k] = tid;
    }

    if (tid == LL - 1) g_total[b] = x;
}

// ---------------------------------------------------------------------------
// Kernel 2: expand, 8 contiguous rows per thread with duplicate-source dedup:
// consecutive rows sharing the same source idx reuse the loaded register
// (avg duration ~3.5 -> ~60% of gather LDGs eliminated). Streaming stores.
// ---------------------------------------------------------------------------
__global__ void __launch_bounds__(384, 3)
lr_expand_kernel(const float* __restrict__ hid,
                 float* __restrict__ out,
                 float* __restrict__ mask,
                 int T) {
    const int lane = threadIdx.x;           // 0..95
    const int b = blockIdx.y;
    const int t0 = blockIdx.x * TILE_T + threadIdx.y * RPT;
    if (t0 >= T) return;

    const int total = g_total[b];

    // idx loads: always in-bounds and 16B-aligned (stride T_MAX, t0 % 8 == 0)
    const int* __restrict__ idx_row = g_idx + b * T_MAX;
    int idx[RPT];
    *(int4*)(&idx[0]) = *(const int4*)(idx_row + t0);
    *(int4*)(&idx[4]) = *(const int4*)(idx_row + t0 + 4);

    const float4* __restrict__ src =
        (const float4*)(hid) + (long long)b * LL * H4 + lane;
    const float4 z = make_float4(0.f, 0.f, 0.f, 0.f);

    // Front-batched gathers, skipping duplicates of the previous row.
    float4 v[RPT];
    #pragma unroll
    for (int k = 0; k < RPT; k++) {
        float4 vv = z;
        const bool live = (t0 + k < total);
        const bool dup = (k > 0) && (idx[k] == idx[k - 1]);
        if (live && !dup) vv = src[idx[k] * H4];
        v[k] = vv;
    }
    // Propagate duplicates (sequential, handles chains). Guard with `live`:
    // rows beyond total must stay zero. Monotonic total => if t0+k < total
    // then t0+k-1 < total, so v[k-1] is valid data.
    #pragma unroll
    for (int k = 1; k < RPT; k++) {
        if ((t0 + k < total) && (idx[k] == idx[k - 1])) v[k] = v[k - 1];
    }

    float4* __restrict__ dst =
        (float4*)(out) + ((long long)b * T + t0) * H4 + lane;

    if (t0 + RPT <= T) {
        #pragma unroll
        for (int k = 0; k < RPT; k++) __stcs(dst + k * H4, v[k]);

        if (lane == 0) {
            float4 m0, m1;
            m0.x = (t0 + 0 < total) ? 1.f : 0.f;
            m0.y = (t0 + 1 < total) ? 1.f : 0.f;
            m0.z = (t0 + 2 < total) ? 1.f : 0.f;
            m0.w = (t0 + 3 < total) ? 1.f : 0.f;
            m1.x = (t0 + 4 < total) ? 1.f : 0.f;
            m1.y = (t0 + 5 < total) ? 1.f : 0.f;
            m1.z = (t0 + 6 < total) ? 1.f : 0.f;
            m1.w = (t0 + 7 < total) ? 1.f : 0.f;
            float4* mp = (float4*)(mask + (long long)b * T + t0);
            __stcs(mp, m0);
            __stcs(mp + 1, m1);
        }
    } else {
        // T-tail: per-row bounds
        #pragma unroll
        for (int k = 0; k < RPT; k++) {
            if (t0 + k < T) {
                __stcs(dst + k * H4, v[k]);
                if (lane == 0)
                    mask[(long long)b * T + t0 + k] = (t0 + k < total) ? 1.f : 0.f;
            }
        }
    }
}

// ---------------------------------------------------------------------------
extern "C" void kernel_launch(void* const* d_in, const int* in_sizes, int n_in,
                              void* d_out, int out_size) {
    const float* hid = (const float*)d_in[0];   // (B, L, H) f32
    const int*   dur = (const int*)d_in[1];     // (B, L) i32

    // out_size = B*T*H + B*T = B*T*(H+1)
    const int T = out_size / (BB * (HH + 1));
    const long long n_rows = (long long)BB * T;

    float* out  = (float*)d_out;                // B*T*H
    float* mask = (float*)d_out + n_rows * HH;  // B*T

    lr_scan_scatter_kernel<<<BB, LL>>>(dur);

    dim3 grid((T + TILE_T - 1) / TILE_T, BB);
    dim3 blk(H4, 4);
    lr_expand_kernel<<<grid, blk>>>(hid, out, mask, T);
}